// round 3
// baseline (speedup 1.0000x reference)
#include <cuda_runtime.h>

// Fixed shapes
#define KDIM   51
#define BDIM   256
#define CCOLS  24576             // 8192 points * 3
#define TB     128               // batch rows per block
#define TC     128               // columns per block
#define GRIDX  (CCOLS / TC)      // 192
#define GRIDY  (BDIM / TB)       // 2
#define NBLK   (GRIDX * GRIDY)   // 384
#define EPSF   1e-6f
#define MULTF  0.0025f

// Dynamic smem: w2 tile [51][128] float2 then bs tile [51][128] float
#define W2_BYTES (KDIM * TB * 8)           // 52224
#define BS_BYTES (KDIM * TC * 4)           // 26112
#define SMEM_BYTES (W2_BYTES + BS_BYTES)   // 78336

// Self-resetting device state (zero-init at load; last block resets).
__device__ float    g_s[BDIM * 3];
__device__ unsigned g_count;
__device__ float2   g_w2[KDIM * BDIM];  // k-major, (w,w) duplicated

typedef unsigned long long ull;

__device__ __forceinline__ ull pack2(float a, float b) {
    ull r; asm("mov.b64 %0, {%1, %2};" : "=l"(r) : "f"(a), "f"(b)); return r;
}
__device__ __forceinline__ void unpack2(ull v, float& a, float& b) {
    asm("mov.b64 {%0, %1}, %2;" : "=f"(a), "=f"(b) : "l"(v));
}
__device__ __forceinline__ void ffma2(ull& d, ull a, ull b) {
    asm("fma.rn.f32x2 %0, %1, %2, %0;" : "+l"(d) : "l"(a), "l"(b));
}

// Prologue: packed k-major weights, fully coalesced 8B writes.
__global__ void diff_kernel(const float* __restrict__ y_hat,
                            const float* __restrict__ y) {
    const int k = blockIdx.x;
    const int b = threadIdx.x;
    float d = __ldg(&y_hat[b * KDIM + k]) - __ldg(&y[b * KDIM + k]);
    g_w2[k * BDIM + b] = make_float2(d, d);
}

// Register-tiled GEMM + squared reduce + last-block finish.
// grid (192, 2), block 256 = 16 bt x 16 ct; thread tile 8b x 8c.
__global__ void __launch_bounds__(256, 2)
pointloss_main(const float* __restrict__ bs, float* __restrict__ out) {
    extern __shared__ char smem_raw[];
    float2* w2_s = reinterpret_cast<float2*>(smem_raw);             // [51*128]
    float*  bs_s = reinterpret_cast<float*>(smem_raw + W2_BYTES);   // [51*128]
    __shared__ bool  s_last;
    __shared__ float red[8];

    const int tid  = threadIdx.x;
    const int bt   = tid >> 4;        // 0..15
    const int ct   = tid & 15;        // 0..15
    const int b0l  = bt * 8;          // local b base
    const int brow = blockIdx.y;
    const int cblk = blockIdx.x * TC; // global col base of tile
    const int c0g  = cblk + ct * 8;   // this thread's global col base

    // Copy w2 slab (rows k, 128 b's of this brow): 8B coalesced.
    for (int i = tid; i < KDIM * TB; i += 256) {
        int k  = i >> 7;
        int bl = i & 127;
        w2_s[i] = g_w2[k * BDIM + brow * TB + bl];
    }
    // Copy bs tile: float4 coalesced (cblk*4 bytes is 512B aligned).
    for (int i = tid; i < KDIM * (TC / 4); i += 256) {
        int k  = i >> 5;
        int c4 = i & 31;
        reinterpret_cast<float4*>(bs_s)[i] =
            *reinterpret_cast<const float4*>(bs + (size_t)k * CCOLS + cblk + c4 * 4);
    }
    __syncthreads();

    // Accumulators: 8 b x 4 col-pairs, init to (EPS, EPS).
    const ull eps2 = pack2(EPSF, EPSF);
    ull acc[8][4];
#pragma unroll
    for (int bi = 0; bi < 8; bi++)
#pragma unroll
        for (int cp = 0; cp < 4; cp++) acc[bi][cp] = eps2;

#pragma unroll 1
    for (int k = 0; k < KDIM; k++) {
        // 8 duplicated weights: 64B = 4 LDS.128 (2 distinct addrs/warp).
        const longlong2* wp =
            reinterpret_cast<const longlong2*>(w2_s + k * TB + b0l);
        longlong2 w01 = wp[0], w23 = wp[1], w45 = wp[2], w67 = wp[3];
        ull w[8] = {(ull)w01.x, (ull)w01.y, (ull)w23.x, (ull)w23.y,
                    (ull)w45.x, (ull)w45.y, (ull)w67.x, (ull)w67.y};
        // 4 bs col-pairs: 32B = 2 LDS.128.
        const longlong2* cp128 =
            reinterpret_cast<const longlong2*>(bs_s + k * TC + ct * 8);
        longlong2 ca = cp128[0], cb = cp128[1];
        ull c[4] = {(ull)ca.x, (ull)ca.y, (ull)cb.x, (ull)cb.y};

#pragma unroll
        for (int bi = 0; bi < 8; bi++)
#pragma unroll
            for (int cp = 0; cp < 4; cp++)
                ffma2(acc[bi][cp], w[bi], c[cp]);
    }

    // Square into slot space (slot j = local col offset mod 3; compile-time).
    float sq[8][3];
#pragma unroll
    for (int bi = 0; bi < 8; bi++) { sq[bi][0] = sq[bi][1] = sq[bi][2] = 0.0f; }
#pragma unroll
    for (int bi = 0; bi < 8; bi++) {
#pragma unroll
        for (int cp = 0; cp < 4; cp++) {
            float a, b;
            unpack2(acc[bi][cp], a, b);
            sq[bi][(2 * cp) % 3]     += a * a;
            sq[bi][(2 * cp + 1) % 3] += b * b;
        }
    }

    // Remap slots to physical d: d(slot j) = (r + j) % 3, r = c0g % 3.
    const int r = c0g % 3;
    float s0[8], s1[8], s2[8];
#pragma unroll
    for (int bi = 0; bi < 8; bi++) {
        float q0 = sq[bi][0], q1 = sq[bi][1], q2 = sq[bi][2];
        s0[bi] = (r == 0) ? q0 : ((r == 1) ? q2 : q1);
        s1[bi] = (r == 0) ? q1 : ((r == 1) ? q0 : q2);
        s2[bi] = (r == 0) ? q2 : ((r == 1) ? q1 : q0);
    }

    // Reduce across the 16 ct-lanes (consecutive lanes in half-warp).
#pragma unroll
    for (int off = 1; off < 16; off <<= 1) {
#pragma unroll
        for (int bi = 0; bi < 8; bi++) {
            s0[bi] += __shfl_xor_sync(0xFFFFFFFFu, s0[bi], off);
            s1[bi] += __shfl_xor_sync(0xFFFFFFFFu, s1[bi], off);
            s2[bi] += __shfl_xor_sync(0xFFFFFFFFu, s2[bi], off);
        }
    }
    if (ct == 0) {
#pragma unroll
        for (int bi = 0; bi < 8; bi++) {
            int bg = brow * TB + b0l + bi;
            atomicAdd(&g_s[bg * 3 + 0], s0[bi]);
            atomicAdd(&g_s[bg * 3 + 1], s1[bi]);
            atomicAdd(&g_s[bg * 3 + 2], s2[bi]);
        }
    }

    // ---- last-block finish ----
    __syncthreads();
    if (tid == 0) {
        __threadfence();
        unsigned old = atomicAdd(&g_count, 1u);
        s_last = (old == (unsigned)(NBLK - 1));
    }
    __syncthreads();
    if (!s_last) return;

    float v = 0.0f;
    for (int i = tid; i < BDIM * 3; i += 256)
        v += sqrtf(atomicAdd(&g_s[i], 0.0f));
#pragma unroll
    for (int o = 16; o > 0; o >>= 1)
        v += __shfl_down_sync(0xFFFFFFFFu, v, o);
    if ((tid & 31) == 0) red[tid >> 5] = v;
    __syncthreads();
    if (tid < 32) {
        float x = (tid < 8) ? red[tid] : 0.0f;
#pragma unroll
        for (int o = 4; o > 0; o >>= 1)
            x += __shfl_down_sync(0xFFu, x, o);
        if (tid == 0) out[0] = x * MULTF;
    }

    // Reset state for next graph replay.
    __syncthreads();
    for (int i = tid; i < BDIM * 3; i += 256) g_s[i] = 0.0f;
    if (tid == 0) g_count = 0u;
}

extern "C" void kernel_launch(void* const* d_in, const int* in_sizes, int n_in,
                              void* d_out, int out_size) {
    const float* y_hat = (const float*)d_in[0];  // [256, 51]
    const float* y     = (const float*)d_in[1];  // [256, 51]
    // d_in[2] = face — cancels out, unused
    const float* bs    = (const float*)d_in[3];  // [51, 8192, 3]
    float* out = (float*)d_out;

    static bool attr_set = false;
    if (!attr_set) {
        cudaFuncSetAttribute(pointloss_main,
                             cudaFuncAttributeMaxDynamicSharedMemorySize,
                             SMEM_BYTES);
        attr_set = true;
    }

    diff_kernel<<<KDIM, BDIM>>>(y_hat, y);
    dim3 grid(GRIDX, GRIDY);
    pointloss_main<<<grid, 256, SMEM_BYTES>>>(bs, out);
}

// round 4
// speedup vs baseline: 2.0222x; 2.0222x over previous
#include <cuda_runtime.h>

// Fixed shapes
#define KDIM   51
#define KP     52                // padded K (row 51 = ones, carries EPS exactly)
#define BDIM   256
#define CCOLS  24576             // 8192 points * 3
#define TCOLS  192               // columns per gram block (64 per d)
#define GBLKS  (CCOLS / TCOLS)   // 128
#define COLS_D 64                // columns per d per block
#define CPAD   56                // padded k-extent per smem column
#define NTILE  13                // 52/4 k-tiles
#define NPAIRT 91                // upper-tri tile pairs
#define NCOMBO 273               // 91 * 3 d
#define EPSF   1e-6f
#define MULTF  0.0025f

// Global Gram tensor G[d][k][k'] (upper triangle valid) + scalar accumulator.
__device__ __align__(16) float g_G[3 * KP * KP];   // 8112 floats
__device__ float g_out;

__global__ void zero_kernel() {
    int i = blockIdx.x * 256 + threadIdx.x;
    if (i < 3 * KP * KP) g_G[i] = 0.0f;
    if (i == 0) g_out = 0.0f;
}

// Gram kernel: G_d += A_tile A_tile^T for each d-class of columns.
// grid = 128, block = 256. smem layout k-contiguous: As[d][col][k] (pad 56).
__global__ void __launch_bounds__(256)
gram_kernel(const float* __restrict__ bs) {
    __shared__ __align__(16) float As[3 * COLS_D * CPAD];  // 43008 B

    const int tid = threadIdx.x;
    const int c0  = blockIdx.x * TCOLS;

    // Load 51 real rows, de-interleaved by d = c%3, k-contiguous.
    for (int idx = tid; idx < KDIM * TCOLS; idx += 256) {
        int k = idx / TCOLS;
        int c = idx - k * TCOLS;
        float v = __ldg(&bs[(size_t)k * CCOLS + c0 + c]);
        int d = c % 3, col = c / 3;
        As[(d * COLS_D + col) * CPAD + k] = v;
    }
    // Ones row (k = 51) — makes G carry the EPS cross & square terms exactly.
    for (int idx = tid; idx < TCOLS; idx += 256) {
        int d = idx % 3, col = idx / 3;
        As[(d * COLS_D + col) * CPAD + KDIM] = 1.0f;
    }
    __syncthreads();

    // 273 combos = (upper-tri 4x4 k-tile) x (d). Threads 0..16 take a second one.
    for (int combo = tid; combo < NCOMBO; combo += 256) {
        int d    = combo / NPAIRT;
        int tile = combo - d * NPAIRT;
        int ti = 0, rem = tile;
        while (rem >= NTILE - ti) { rem -= NTILE - ti; ti++; }
        int tj = ti + rem;  // ti <= tj

        float acc[4][4];
#pragma unroll
        for (int r = 0; r < 4; r++)
#pragma unroll
            for (int s = 0; s < 4; s++) acc[r][s] = 0.0f;

        const float* base = As + d * COLS_D * CPAD;
#pragma unroll 4
        for (int col = 0; col < COLS_D; col++) {
            // Two aligned LDS.128 per column: a = k-rows [4ti..4ti+3], b = [4tj..].
            float4 a = *reinterpret_cast<const float4*>(base + col * CPAD + ti * 4);
            float4 b = *reinterpret_cast<const float4*>(base + col * CPAD + tj * 4);
            acc[0][0] += a.x * b.x; acc[0][1] += a.x * b.y;
            acc[0][2] += a.x * b.z; acc[0][3] += a.x * b.w;
            acc[1][0] += a.y * b.x; acc[1][1] += a.y * b.y;
            acc[1][2] += a.y * b.z; acc[1][3] += a.y * b.w;
            acc[2][0] += a.z * b.x; acc[2][1] += a.z * b.y;
            acc[2][2] += a.z * b.z; acc[2][3] += a.z * b.w;
            acc[3][0] += a.w * b.x; acc[3][1] += a.w * b.y;
            acc[3][2] += a.w * b.z; acc[3][3] += a.w * b.w;
        }

        // Vector reductions: row r -> G[d][4ti+r][4tj..4tj+3] (16B aligned).
#pragma unroll
        for (int r = 0; r < 4; r++) {
            float4 v = make_float4(acc[r][0], acc[r][1], acc[r][2], acc[r][3]);
            atomicAdd(reinterpret_cast<float4*>(
                          &g_G[d * KP * KP + (ti * 4 + r) * KP + tj * 4]), v);
        }
    }
}

// Quadratic-form kernel: s[b,d] = w~^T G_d w~ (upper-tri form), then sqrt-sum.
// grid = 32 blocks, 256 threads = 8 warps; warp wid handles b = blk*8 + wid.
__global__ void __launch_bounds__(256)
quad_kernel(const float* __restrict__ y_hat, const float* __restrict__ y) {
    __shared__ float G_s[3 * KP * KP];  // 32448 B
    __shared__ float w_s[8][KP];

    const int tid = threadIdx.x;
    const int b0  = blockIdx.x * 8;

    for (int i = tid; i < 3 * KP * KP; i += 256) G_s[i] = g_G[i];
    for (int i = tid; i < 8 * KP; i += 256) {
        int bl = i / KP, k = i - bl * KP;
        w_s[bl][k] = (k < KDIM)
            ? __ldg(&y_hat[(b0 + bl) * KDIM + k]) - __ldg(&y[(b0 + bl) * KDIM + k])
            : EPSF;
    }
    __syncthreads();

    const int wid  = tid >> 5;
    const int lane = tid & 31;
    const int k1   = lane;          // first owned column
    const int k2v  = lane + 32;     // second owned column (valid if < 52)
    const bool has2 = (k2v < KP);
    const int k2   = has2 ? k2v : KDIM;  // clamped in-bounds for loads

    const float* w = w_s[wid];
    const float wk1 = w[k1];
    const float wk2 = has2 ? w[k2v] : 0.0f;

    float total = 0.0f;
    for (int d = 0; d < 3; d++) {
        const float* G = G_s + d * KP * KP;
        float t1 = 0.0f, t2 = 0.0f;
#pragma unroll 4
        for (int k = 0; k < KP; k++) {
            float wk = w[k];
            float g1 = G[k * KP + k1];   // lanes consecutive -> conflict-free
            float g2 = G[k * KP + k2];
            float f1 = (k < k1)  ? wk : ((k == k1)  ? 0.5f * wk : 0.0f);
            float f2 = (k < k2v) ? wk : ((k == k2v) ? 0.5f * wk : 0.0f);
            t1 += g1 * f1;
            t2 += g2 * f2;
        }
        float p = 2.0f * (wk1 * t1 + wk2 * t2);
#pragma unroll
        for (int o = 16; o > 0; o >>= 1)
            p += __shfl_down_sync(0xFFFFFFFFu, p, o);
        if (lane == 0) total += sqrtf(p);
    }
    if (lane == 0) atomicAdd(&g_out, total);
}

__global__ void writeout_kernel(float* __restrict__ out) {
    out[0] = g_out * MULTF;
}

extern "C" void kernel_launch(void* const* d_in, const int* in_sizes, int n_in,
                              void* d_out, int out_size) {
    const float* y_hat = (const float*)d_in[0];  // [256, 51]
    const float* y     = (const float*)d_in[1];  // [256, 51]
    // d_in[2] = face — cancels out of the loss, unused
    const float* bs    = (const float*)d_in[3];  // [51, 8192, 3]
    float* out = (float*)d_out;

    zero_kernel<<<32, 256>>>();
    gram_kernel<<<GBLKS, 256>>>(bs);
    quad_kernel<<<BDIM / 8, 256>>>(y_hat, y);
    writeout_kernel<<<1, 1>>>(out);
}

// round 5
// speedup vs baseline: 2.1287x; 1.0526x over previous
#include <cuda_runtime.h>

// Fixed shapes
#define KDIM   51
#define KP     52                // padded K (row 51 = ones, carries EPS exactly)
#define BDIM   256
#define CCOLS  24576             // 8192 points * 3
#define TCOLS  192               // columns per gram block (64 per d)
#define GBLKS  128               // gram blocks (all co-resident: 128 <= 148 SMs)
#define QBLKS  32                // blocks that continue into the quad phase
#define COLS_D 64                // columns per d per block
#define CPAD   56                // padded k-extent per smem column
#define NTILE  13                // 52/4 k-tiles
#define NPAIRT 91                // upper-tri tile pairs
#define NCOMBO 273               // 91 * 3 d
#define EPSF   1e-6f
#define MULTF  0.0025f

// Self-resetting device state (zero-init at module load; the finisher block
// resets everything at the end of each run, so graph replays start clean).
__device__ __align__(16) float g_G[3 * KP * KP];   // 8112 floats
__device__ float    g_out;
__device__ unsigned g_ctr1;   // gram-done counter
__device__ unsigned g_ctr2;   // quad-done counter

__global__ void __launch_bounds__(256)
fused_kernel(const float* __restrict__ bs,
             const float* __restrict__ y_hat,
             const float* __restrict__ y,
             float* __restrict__ out) {
    // Shared buffer, reused across phases:
    //   phase 1: As[3][COLS_D][CPAD]  (10752 floats)
    //   phase 2: G_s[3*KP*KP] (8112) + w_s[8][KP] (416)
    __shared__ __align__(16) float smem[3 * COLS_D * CPAD];
    __shared__ bool s_last;

    const int tid = threadIdx.x;
    const int blk = blockIdx.x;

    // ======================= Phase 1: Gram =======================
    {
        const int c0 = blk * TCOLS;
        // Load 51 real rows, de-interleaved by d = c%3, k-contiguous.
        for (int idx = tid; idx < KDIM * TCOLS; idx += 256) {
            int k = idx / TCOLS;
            int c = idx - k * TCOLS;
            float v = __ldg(&bs[(size_t)k * CCOLS + c0 + c]);
            int d = c % 3, col = c / 3;
            smem[(d * COLS_D + col) * CPAD + k] = v;
        }
        // Ones row (k = 51): carries the EPS cross & square terms exactly.
        for (int idx = tid; idx < TCOLS; idx += 256) {
            int d = idx % 3, col = idx / 3;
            smem[(d * COLS_D + col) * CPAD + KDIM] = 1.0f;
        }
        __syncthreads();

        // 273 combos = (upper-tri 4x4 k-tile pair) x d; tids 0..16 take a 2nd.
        for (int combo = tid; combo < NCOMBO; combo += 256) {
            int d    = combo / NPAIRT;
            int tile = combo - d * NPAIRT;
            int ti = 0, rem = tile;
            while (rem >= NTILE - ti) { rem -= NTILE - ti; ti++; }
            int tj = ti + rem;  // ti <= tj

            float acc[4][4];
#pragma unroll
            for (int r = 0; r < 4; r++)
#pragma unroll
                for (int s = 0; s < 4; s++) acc[r][s] = 0.0f;

            const float* base = smem + d * COLS_D * CPAD;
#pragma unroll 4
            for (int col = 0; col < COLS_D; col++) {
                float4 a = *reinterpret_cast<const float4*>(base + col * CPAD + ti * 4);
                float4 b = *reinterpret_cast<const float4*>(base + col * CPAD + tj * 4);
                acc[0][0] += a.x * b.x; acc[0][1] += a.x * b.y;
                acc[0][2] += a.x * b.z; acc[0][3] += a.x * b.w;
                acc[1][0] += a.y * b.x; acc[1][1] += a.y * b.y;
                acc[1][2] += a.y * b.z; acc[1][3] += a.y * b.w;
                acc[2][0] += a.z * b.x; acc[2][1] += a.z * b.y;
                acc[2][2] += a.z * b.z; acc[2][3] += a.z * b.w;
                acc[3][0] += a.w * b.x; acc[3][1] += a.w * b.y;
                acc[3][2] += a.w * b.z; acc[3][3] += a.w * b.w;
            }
#pragma unroll
            for (int r = 0; r < 4; r++) {
                float4 v = make_float4(acc[r][0], acc[r][1], acc[r][2], acc[r][3]);
                atomicAdd(reinterpret_cast<float4*>(
                              &g_G[d * KP * KP + (ti * 4 + r) * KP + tj * 4]), v);
            }
        }
    }
    __syncthreads();
    if (tid == 0) {
        __threadfence();
        atomicAdd(&g_ctr1, 1u);
    }

    // Gram-only blocks are done.
    if (blk >= QBLKS) return;

    // Grid-wide barrier: wait for all 128 gram blocks (all co-resident).
    if (tid == 0) {
        while (atomicAdd(&g_ctr1, 0u) < (unsigned)GBLKS) { }
    }
    __syncthreads();

    // ======================= Phase 2: Quad =======================
    float* G_s = smem;                 // 8112 floats
    float* w_s = smem + 3 * KP * KP;   // 8 * KP floats

    // L2-coherent load of G (skip L1; lines never cached in L1 by this block
    // anyway, but be explicit).
    for (int i = tid; i < 3 * KP * KP; i += 256) G_s[i] = __ldcg(&g_G[i]);
    const int b0 = blk * 8;
    for (int i = tid; i < 8 * KP; i += 256) {
        int bl = i / KP, k = i - bl * KP;
        w_s[bl * KP + k] = (k < KDIM)
            ? __ldg(&y_hat[(b0 + bl) * KDIM + k]) - __ldg(&y[(b0 + bl) * KDIM + k])
            : EPSF;
    }
    __syncthreads();

    const int wid  = tid >> 5;
    const int lane = tid & 31;
    const int k1   = lane;
    const int k2v  = lane + 32;
    const bool has2 = (k2v < KP);
    const int k2   = has2 ? k2v : KDIM;

    const float* w = w_s + wid * KP;
    const float wk1 = w[k1];
    const float wk2 = has2 ? w[k2v] : 0.0f;

    float total = 0.0f;
    for (int d = 0; d < 3; d++) {
        const float* G = G_s + d * KP * KP;
        float t1 = 0.0f, t2 = 0.0f;
#pragma unroll 4
        for (int k = 0; k < KP; k++) {
            float wk = w[k];
            float g1 = G[k * KP + k1];
            float g2 = G[k * KP + k2];
            float f1 = (k < k1)  ? wk : ((k == k1)  ? 0.5f * wk : 0.0f);
            float f2 = (k < k2v) ? wk : ((k == k2v) ? 0.5f * wk : 0.0f);
            t1 += g1 * f1;
            t2 += g2 * f2;
        }
        float p = 2.0f * (wk1 * t1 + wk2 * t2);
#pragma unroll
        for (int o = 16; o > 0; o >>= 1)
            p += __shfl_down_sync(0xFFFFFFFFu, p, o);
        if (lane == 0) total += sqrtf(p);
    }
    if (lane == 0) atomicAdd(&g_out, total);

    // ======================= Finisher =======================
    __syncthreads();
    if (tid == 0) {
        __threadfence();
        unsigned old = atomicAdd(&g_ctr2, 1u);
        s_last = (old == (unsigned)(QBLKS - 1));
    }
    __syncthreads();
    if (!s_last) return;

    if (tid == 0) {
        float v = atomicAdd(&g_out, 0.0f);  // L2-coherent read
        out[0] = v * MULTF;
    }
    // Reset all device state for the next graph replay.
    for (int i = tid; i < 3 * KP * KP; i += 256) g_G[i] = 0.0f;
    if (tid == 0) {
        g_out  = 0.0f;
        g_ctr1 = 0u;
        g_ctr2 = 0u;
    }
}

extern "C" void kernel_launch(void* const* d_in, const int* in_sizes, int n_in,
                              void* d_out, int out_size) {
    const float* y_hat = (const float*)d_in[0];  // [256, 51]
    const float* y     = (const float*)d_in[1];  // [256, 51]
    // d_in[2] = face — cancels out of the loss, unused
    const float* bs    = (const float*)d_in[3];  // [51, 8192, 3]
    float* out = (float*)d_out;

    fused_kernel<<<GBLKS, 256>>>(bs, y_hat, y, out);
}